// round 7
// baseline (speedup 1.0000x reference)
#include <cuda_runtime.h>
#include <limits.h>
#include <stdint.h>

typedef unsigned long long u64;

// Problem constants
#define BATCH 32
#define NPTS  131072            // 2^17
#define BN    (BATCH*NPTS)      // 4194304
#define TSEL  32768
#define CELL  0.05f

// Hash: 2^23 slots of one u64 (key<<32 | minIdx); high word later = rank
#define HBITS 23
#define HSIZE (1<<HBITS)
#define HMASK (HSIZE-1)
#define EMPTY64 0xFFFFFFFFFFFFFFFFull

// Scan config: 1024 blocks x 4096 elements (256 thr x 16)
#define NBLK  1024
#define CHUNK 4096
#define SCANT 256
#define ITEMS 16

// State word: bits[62:64) phase: 0=none, 1=inserted, 2=aggregate, 3=inclusive
#define ST_INS (1ull << 62)
#define ST_AGG (2ull << 62)
#define ST_INC (3ull << 62)
#define PUBBIT (1ull << 63)
#define VALMASK 0x3FFFFFFFull

// Output layout (flattened, concatenated, all f32)
#define OFF_Y    0
#define OFF_IDX  (BATCH*TSEL*3)
#define OFF_MASK (OFF_IDX + BATCH*TSEL*2)
#define OFF_UL   (OFF_MASK + BATCH*TSEL)
#define OFF_ULI  (OFF_UL + BN)

// Scratch
__device__ u64 d_h[HSIZE];             // low: minIdx ; HIGH: key -> rank (after mega)
__device__ int d_slot[BN];
__device__ u64 d_state[NBLK];
__device__ u64 d_bbase[BATCH+1];
__device__ unsigned d_ticket;

__device__ __forceinline__ int quant(float v) {
    return (int)rintf(__fdiv_rn(v, CELL));
}
__device__ __forceinline__ unsigned mkkey(int b, int q0, int q1, int q2) {
    return ((unsigned)b << 27) | ((unsigned)(q0 + 256) << 18)
         | ((unsigned)(q1 + 256) << 9) | (unsigned)(q2 + 256);
}
__device__ __forceinline__ unsigned khash(unsigned k) {
    return (k * 2654435761u) >> (32 - HBITS);
}

// ---------------------------------------------------------------------------
// K1: init hash table + state
__global__ void k_init() {
    unsigned i = blockIdx.x * blockDim.x + threadIdx.x;
    unsigned stride = gridDim.x * blockDim.x;
    ulonglong2* p = (ulonglong2*)d_h;
    const unsigned n = HSIZE / 2;
    for (unsigned j = i; j < n; j += stride)
        p[j] = make_ulonglong2(EMPTY64, EMPTY64);
    if (i < NBLK) d_state[i] = 0;
    if (i <= BATCH) d_bbase[i] = 0;
    if (i == 0) d_ticket = 0;
}

// ---------------------------------------------------------------------------
// K2: MEGA — insert (batched CAS, MLP=8) + ticket wait + flags + lookback scan
//     + scatters (rank->high word, ULI, selected y/idx/mask from key)
__global__ void __launch_bounds__(SCANT) k_mega(const float* __restrict__ x,
                                                float* __restrict__ out) {
    __shared__ int s_tb;
    __shared__ int wsum[8];
    __shared__ int wexc[8];
    __shared__ int s_total;
    __shared__ unsigned s_excl, s_pb;

    int t = threadIdx.x;
    if (t == 0) s_tb = (int)atomicAdd(&d_ticket, 1u);
    __syncthreads();
    int tb = s_tb;
    int i0 = tb * CHUNK + t * ITEMS;
    int b  = i0 >> 17;                       // whole chunk in one batch

    // ---- insert phase: two half-batches of 8 points ----
    unsigned hh[ITEMS];
    #pragma unroll
    for (int half = 0; half < 2; half++) {
        int e0 = half * 8;
        // load 6 float4 = 24 floats = 8 points
        float px[24];
        const float4* xv = (const float4*)(x + 3 * (i0 + e0));
        #pragma unroll
        for (int v = 0; v < 6; v++) {
            float4 f4 = __ldg(&xv[v]);
            px[4*v+0] = f4.x; px[4*v+1] = f4.y; px[4*v+2] = f4.z; px[4*v+3] = f4.w;
        }
        unsigned key[8];
        unsigned h8[8];
        #pragma unroll
        for (int e = 0; e < 8; e++) {
            int q0 = quant(px[3*e+0]);
            int q1 = quant(px[3*e+1]);
            int q2 = quant(px[3*e+2]);
            key[e] = mkkey(b, q0, q1, q2);
            h8[e] = khash(key[e]);
        }
        u64 old8[8];
        #pragma unroll
        for (int e = 0; e < 8; e++) {
            u64 val = ((u64)key[e] << 32) | (unsigned)(i0 + e0 + e);
            old8[e] = atomicCAS(&d_h[h8[e]], EMPTY64, val);
        }
        #pragma unroll
        for (int e = 0; e < 8; e++) {
            int i = i0 + e0 + e;
            u64 val = ((u64)key[e] << 32) | (unsigned)i;
            u64 o = old8[e];
            unsigned h = h8[e];
            while (true) {
                if (o == EMPTY64) break;
                if ((unsigned)(o >> 32) == key[e]) {
                    if ((unsigned)o > (unsigned)i)
                        atomicMin(&d_h[h], val);
                    break;
                }
                h = (h + 1) & HMASK;
                o = atomicCAS(&d_h[h], EMPTY64, val);
            }
            hh[e0 + e] = h;
        }
    }
    #pragma unroll
    for (int v = 0; v < 4; v++)
        *(uint4*)(d_slot + i0 + 4*v) = make_uint4(hh[4*v+0], hh[4*v+1], hh[4*v+2], hh[4*v+3]);

    __threadfence();
    __syncthreads();
    if (t == 0) atomicExch(&d_state[tb], ST_INS);

    // ---- wait: all earlier tickets inserted (parallel poll) ----
    for (int j = t; j < tb; j += SCANT) {
        while (*(volatile u64*)&d_state[j] < ST_INS) { }
    }
    __syncthreads();

    // ---- flags: low word == own index ----
    const unsigned* hlow = (const unsigned*)d_h;
    unsigned fmask = 0;
    int c = 0;
    #pragma unroll
    for (int e = 0; e < ITEMS; e++) {
        unsigned low = __ldcg(hlow + 2 * hh[e]);
        unsigned f = (low == (unsigned)(i0 + e));
        fmask |= f << e;
        c += (int)f;
    }

    // ---- block scan ----
    int lane = t & 31, wid = t >> 5;
    int inc = c;
    #pragma unroll
    for (int o = 1; o < 32; o <<= 1) {
        int u = __shfl_up_sync(0xFFFFFFFFu, inc, o);
        if (lane >= o) inc += u;
    }
    if (lane == 31) wsum[wid] = inc;
    __syncthreads();
    if (t < 8) {
        int val = wsum[t];
        int ic = val;
        #pragma unroll
        for (int o = 1; o < 8; o <<= 1) {
            int u = __shfl_up_sync(0xFFu, ic, o);
            if (t >= o) ic += u;
        }
        wexc[t] = ic - val;
        if (t == 7) s_total = ic;
    }
    __syncthreads();
    int agg = s_total;

    // ---- decoupled lookback (thread 0) ----
    if (t == 0) {
        unsigned excl = 0;
        if (tb == 0) {
            __threadfence();
            atomicExch(&d_state[0], ST_INC | (u64)agg);
        } else {
            atomicExch(&d_state[tb], ST_AGG | (u64)agg);
            int j = tb - 1;
            while (true) {
                u64 s = *(volatile u64*)&d_state[j];
                u64 f = s >> 62;
                if (f < 2) continue;
                excl += (unsigned)(s & VALMASK);
                if (f == 3) break;
                j--;
            }
            __threadfence();
            atomicExch(&d_state[tb], ST_INC | (u64)(excl + (unsigned)agg));
        }
        int m = tb >> 5;
        unsigned pbv;
        if ((tb & 31) == 0) {
            __threadfence();
            atomicExch(&d_bbase[m], PUBBIT | (u64)excl);
            pbv = excl;
        } else {
            while (true) {
                u64 s = *(volatile u64*)&d_bbase[m];
                if (s & PUBBIT) { pbv = (unsigned)(s & VALMASK); break; }
            }
        }
        if (tb == NBLK - 1) {
            __threadfence();
            atomicExch(&d_bbase[BATCH], PUBBIT | (u64)(excl + (unsigned)agg));
        }
        s_excl = excl;
        s_pb = pbv;
    }
    __syncthreads();

    int thOff = (int)s_excl + wexc[wid] + (inc - c);
    int pb = (int)s_pb;
    unsigned* hw = (unsigned*)d_h;

    // ---- scatter: firsts only ----
    #pragma unroll
    for (int e = 0; e < ITEMS; e++) {
        if ((fmask >> e) & 1) {
            int i = i0 + e;
            int p = thOff + __popc(fmask & ((1u << e) - 1u));
            unsigned key = __ldcg(hw + 2 * hh[e] + 1);   // key still there (only we write it)
            hw[2 * hh[e] + 1] = (unsigned)p;             // rank -> HIGH word
            out[OFF_ULI + p] = (float)i;
            int r = p - pb;
            if (r < TSEL) {
                int il = i & (NPTS - 1);
                float y0 = CELL * (float)((int)((key >> 18) & 511) - 256);
                float y1 = CELL * (float)((int)((key >> 9) & 511) - 256);
                float y2 = CELL * (float)((int)(key & 511) - 256);
                int o = b * TSEL + r;
                out[OFF_Y + 3*o + 0] = y0;
                out[OFF_Y + 3*o + 1] = y1;
                out[OFF_Y + 3*o + 2] = y2;
                out[OFF_IDX + 2*o + 0] = (float)b;
                out[OFF_IDX + 2*o + 1] = (float)il;
                out[OFF_MASK + o] = 1.0f;
            }
        }
    }
}

// ---------------------------------------------------------------------------
// K3: ul_idx for ALL points, branch-free: rank = high word of entry
__global__ void k_ul(float* __restrict__ out) {
    int t = threadIdx.x;
    int i0 = blockIdx.x * CHUNK + t * ITEMS;
    const unsigned* hw = (const unsigned*)d_h;
    #pragma unroll
    for (int v = 0; v < 4; v++) {
        int4 sl = *(const int4*)(d_slot + i0 + 4*v);
        float r0 = (float)__ldcg(hw + 2*sl.x + 1);
        float r1 = (float)__ldcg(hw + 2*sl.y + 1);
        float r2 = (float)__ldcg(hw + 2*sl.z + 1);
        float r3 = (float)__ldcg(hw + 2*sl.w + 1);
        *(float4*)(out + OFF_UL + i0 + 4*v) = make_float4(r0, r1, r2, r3);
    }
}

// ---------------------------------------------------------------------------
// K4: fixup — ULI SENT tail + (dormant) deficient-batch non-first fill
__global__ void k_fixup(const float* __restrict__ x, float* __restrict__ out) {
    int blk = blockIdx.x;
    int t = threadIdx.x;
    if (blk >= BATCH) {
        int U = (int)(d_bbase[BATCH] & VALMASK);
        int nb = gridDim.x - BATCH;
        for (int i = U + (blk - BATCH) * blockDim.x + t; i < BN; i += nb * blockDim.x)
            out[OFF_ULI + i] = (float)BN;
        return;
    }
    int pb0 = (int)(d_bbase[blk] & VALMASK);
    int pb1 = (int)(d_bbase[blk + 1] & VALMASK);
    int Kb = pb1 - pb0;
    if (Kb >= TSEL) return;   // normal case

    // Dormant slow path: sequential chunked scan over this batch's points
    __shared__ int s_run;
    __shared__ int cw[8];
    const unsigned* hlow = (const unsigned*)d_h;
    if (t == 0) s_run = 0;
    __syncthreads();
    for (int base = 0; base < NPTS; base += SCANT) {
        int il = base + t;
        int i = blk * NPTS + il;
        int sl = d_slot[i];
        int isf = (__ldcg(hlow + 2*sl) == (unsigned)i);
        int lane = t & 31, wid = t >> 5;
        int incv = isf;
        #pragma unroll
        for (int o = 1; o < 32; o <<= 1) {
            int u = __shfl_up_sync(0xFFFFFFFFu, incv, o);
            if (lane >= o) incv += u;
        }
        if (lane == 31) cw[wid] = incv;
        __syncthreads();
        int woff = 0;
        for (int k = 0; k < wid; k++) woff += cw[k];
        int r = s_run + woff + incv - isf;
        if (!isf) {
            int tt = Kb + (il - r);
            if (tt < TSEL) {
                float y0 = CELL * rintf(__fdiv_rn(__ldg(&x[3*i+0]), CELL));
                float y1 = CELL * rintf(__fdiv_rn(__ldg(&x[3*i+1]), CELL));
                float y2 = CELL * rintf(__fdiv_rn(__ldg(&x[3*i+2]), CELL));
                int o = blk * TSEL + tt;
                out[OFF_Y + 3*o + 0] = y0;
                out[OFF_Y + 3*o + 1] = y1;
                out[OFF_Y + 3*o + 2] = y2;
                out[OFF_IDX + 2*o + 0] = (float)blk;
                out[OFF_IDX + 2*o + 1] = (float)il;
                out[OFF_MASK + o] = 0.0f;
            }
        }
        __syncthreads();
        if (t == 0) {
            int tot = 0;
            #pragma unroll
            for (int k = 0; k < 8; k++) tot += cw[k];
            s_run += tot;
        }
        __syncthreads();
    }
}

// ---------------------------------------------------------------------------
extern "C" void kernel_launch(void* const* d_in, const int* in_sizes, int n_in,
                              void* d_out, int out_size) {
    const float* x = (const float*)d_in[0];
    float* out = (float*)d_out;
    (void)in_sizes; (void)n_in; (void)out_size;

    k_init <<<2048, 512>>>();
    k_mega <<<NBLK, SCANT>>>(x, out);
    k_ul   <<<NBLK, SCANT>>>(out);
    k_fixup<<<BATCH + 64, SCANT>>>(x, out);
}

// round 8
// speedup vs baseline: 3.9147x; 3.9147x over previous
#include <cuda_runtime.h>
#include <limits.h>
#include <stdint.h>

typedef unsigned long long u64;

// Problem constants
#define BATCH 32
#define NPTS  131072            // 2^17
#define BN    (BATCH*NPTS)      // 4194304
#define TSEL  32768
#define CELL  0.05f

// Hash: 2^23 slots of one u64 (key<<32 | minIdx); high word later = rank
#define HBITS 23
#define HSIZE (1<<HBITS)
#define HMASK (HSIZE-1)
#define EMPTY64 0xFFFFFFFFFFFFFFFFull

// Scan config: 1024 blocks x 4096 elements (256 thr x 16)
#define NBLK  1024
#define CHUNK 4096
#define SCANT 256
#define ITEMS 16

// Lookback state flags
#define FLAG1 (1ull << 62)
#define FLAG2 (2ull << 62)
#define SFMASK (3ull << 62)
#define PUBBIT (1ull << 63)
#define VALMASK 0x3FFFFFFFull

// Output layout (flattened, concatenated, all f32)
#define OFF_Y    0
#define OFF_IDX  (BATCH*TSEL*3)
#define OFF_MASK (OFF_IDX + BATCH*TSEL*2)
#define OFF_UL   (OFF_MASK + BATCH*TSEL)
#define OFF_ULI  (OFF_UL + BN)

// Scratch
__device__ u64 d_h[HSIZE];             // low: minIdx ; HIGH: key -> rank (after fused)
__device__ int d_slot[BN];
__device__ u64 d_state[NBLK];
__device__ u64 d_bbase[BATCH+1];
__device__ unsigned d_ticket;

__device__ __forceinline__ int quant(float v) {
    return (int)rintf(__fdiv_rn(v, CELL));
}
__device__ __forceinline__ unsigned mkkey(int b, int q0, int q1, int q2) {
    return ((unsigned)b << 27) | ((unsigned)(q0 + 256) << 18)
         | ((unsigned)(q1 + 256) << 9) | (unsigned)(q2 + 256);
}
__device__ __forceinline__ unsigned khash(unsigned k) {
    return (k * 2654435761u) >> (32 - HBITS);
}

// ---------------------------------------------------------------------------
// K1: init hash table + lookback state
__global__ void k_init() {
    unsigned i = blockIdx.x * blockDim.x + threadIdx.x;
    unsigned stride = gridDim.x * blockDim.x;
    ulonglong2* p = (ulonglong2*)d_h;
    const unsigned n = HSIZE / 2;
    for (unsigned j = i; j < n; j += stride)
        p[j] = make_ulonglong2(EMPTY64, EMPTY64);
    if (i < NBLK) d_state[i] = 0;
    if (i <= BATCH) d_bbase[i] = 0;
    if (i == 0) d_ticket = 0;
}

// ---------------------------------------------------------------------------
// K2: insert, CAS-first probing (completes fully before any rank writes)
__global__ void k_insert(const float* __restrict__ x) {
    int i = blockIdx.x * blockDim.x + threadIdx.x;   // [0, BN)
    float x0 = __ldcs(&x[3*i+0]);
    float x1 = __ldcs(&x[3*i+1]);
    float x2 = __ldcs(&x[3*i+2]);
    int q0 = quant(x0), q1 = quant(x1), q2 = quant(x2);
    int b = i >> 17;
    unsigned key = mkkey(b, q0, q1, q2);
    u64 val = ((u64)key << 32) | (unsigned)i;
    unsigned h = khash(key);
    while (true) {
        u64 old = atomicCAS(&d_h[h], EMPTY64, val);
        if (old == EMPTY64) break;
        if ((unsigned)(old >> 32) == key) {
            if ((unsigned)old > (unsigned)i)
                atomicMin(&d_h[h], val);
            break;
        }
        h = (h + 1) & HMASK;
    }
    __stcs(&d_slot[i], (int)h);
}

// ---------------------------------------------------------------------------
// K3: fused flags + decoupled-lookback scan + scatters (rank, ULI, y/idx/mask)
__global__ void __launch_bounds__(SCANT) k_fused(float* __restrict__ out) {
    __shared__ int s_tb;
    __shared__ int wsum[8];
    __shared__ int wexc[8];
    __shared__ int s_total;
    __shared__ unsigned s_excl, s_pb;

    int t = threadIdx.x;
    if (t == 0) s_tb = (int)atomicAdd(&d_ticket, 1u);
    __syncthreads();
    int tb = s_tb;
    int i0 = tb * CHUNK + t * ITEMS;

    int ss[ITEMS];
    #pragma unroll
    for (int v = 0; v < 4; v++) {
        int4 sv;
        sv.x = __ldcs(d_slot + i0 + 4*v + 0);
        sv.y = __ldcs(d_slot + i0 + 4*v + 1);
        sv.z = __ldcs(d_slot + i0 + 4*v + 2);
        sv.w = __ldcs(d_slot + i0 + 4*v + 3);
        ss[4*v+0] = sv.x; ss[4*v+1] = sv.y; ss[4*v+2] = sv.z; ss[4*v+3] = sv.w;
    }

    // full entry read: low word -> flag, high word -> key (for y decode)
    unsigned hk[ITEMS];
    unsigned fmask = 0;
    int pre[ITEMS];
    int c = 0;
    #pragma unroll
    for (int e = 0; e < ITEMS; e++) {
        u64 cur = __ldcg(&d_h[ss[e]]);
        unsigned f = ((unsigned)cur == (unsigned)(i0 + e));
        hk[e] = (unsigned)(cur >> 32);
        fmask |= f << e;
        pre[e] = c;
        c += (int)f;
    }

    // block scan of per-thread counts
    int lane = t & 31, wid = t >> 5;
    int inc = c;
    #pragma unroll
    for (int o = 1; o < 32; o <<= 1) {
        int u = __shfl_up_sync(0xFFFFFFFFu, inc, o);
        if (lane >= o) inc += u;
    }
    if (lane == 31) wsum[wid] = inc;
    __syncthreads();
    if (t < 8) {
        int val = wsum[t];
        int ic = val;
        #pragma unroll
        for (int o = 1; o < 8; o <<= 1) {
            int u = __shfl_up_sync(0xFFu, ic, o);
            if (t >= o) ic += u;
        }
        wexc[t] = ic - val;
        if (t == 7) s_total = ic;
    }
    __syncthreads();
    int agg = s_total;

    // decoupled lookback (thread 0)
    if (t == 0) {
        unsigned excl = 0;
        if (tb == 0) {
            __threadfence();
            atomicExch(&d_state[0], FLAG2 | (u64)agg);
        } else {
            atomicExch(&d_state[tb], FLAG1 | (u64)agg);
            int j = tb - 1;
            while (true) {
                u64 s = *(volatile u64*)&d_state[j];
                u64 f = s & SFMASK;
                if (f == 0) continue;
                excl += (unsigned)(s & VALMASK);
                if (f == FLAG2) break;
                j--;
            }
            __threadfence();
            atomicExch(&d_state[tb], FLAG2 | (u64)(excl + (unsigned)agg));
        }
        int m = tb >> 5;
        unsigned pbv;
        if ((tb & 31) == 0) {
            __threadfence();
            atomicExch(&d_bbase[m], PUBBIT | (u64)excl);
            pbv = excl;
        } else {
            while (true) {
                u64 s = *(volatile u64*)&d_bbase[m];
                if (s & PUBBIT) { pbv = (unsigned)(s & VALMASK); break; }
            }
        }
        if (tb == NBLK - 1) {
            __threadfence();
            atomicExch(&d_bbase[BATCH], PUBBIT | (u64)(excl + (unsigned)agg));
        }
        s_excl = excl;
        s_pb = pbv;
    }
    __syncthreads();

    int thOff = (int)s_excl + wexc[wid] + (inc - c);
    int pb = (int)s_pb;
    int b = tb >> 5;
    unsigned* hw = (unsigned*)d_h;   // high words at odd indices: rank storage

    // scatter: firsts only (y decoded from key — exact, matches rint path)
    #pragma unroll
    for (int e = 0; e < ITEMS; e++) {
        if ((fmask >> e) & 1) {
            int i  = i0 + e;
            int p  = thOff + pre[e];
            hw[2 * ss[e] + 1] = (unsigned)p;     // rank -> HIGH word (low stays minIdx)
            __stcs(&out[OFF_ULI + p], (float)i);
            int r = p - pb;
            if (r < TSEL) {
                unsigned key = hk[e];
                int il = i & (NPTS - 1);
                float y0 = CELL * (float)((int)((key >> 18) & 511) - 256);
                float y1 = CELL * (float)((int)((key >> 9) & 511) - 256);
                float y2 = CELL * (float)((int)(key & 511) - 256);
                int o = b * TSEL + r;
                __stcs(&out[OFF_Y + 3*o + 0], y0);
                __stcs(&out[OFF_Y + 3*o + 1], y1);
                __stcs(&out[OFF_Y + 3*o + 2], y2);
                __stcs(&out[OFF_IDX + 2*o + 0], (float)b);
                __stcs(&out[OFF_IDX + 2*o + 1], (float)il);
                __stcs(&out[OFF_MASK + o], 1.0f);
            }
        }
    }
}

// ---------------------------------------------------------------------------
// K4: ul_idx for ALL points, branch-free: rank = high word of L2-resident hash
__global__ void k_ul(float* __restrict__ out) {
    int t = threadIdx.x;
    int i0 = blockIdx.x * CHUNK + t * ITEMS;
    const unsigned* hw = (const unsigned*)d_h;
    #pragma unroll
    for (int v = 0; v < 4; v++) {
        int s0 = __ldcs(d_slot + i0 + 4*v + 0);
        int s1 = __ldcs(d_slot + i0 + 4*v + 1);
        int s2 = __ldcs(d_slot + i0 + 4*v + 2);
        int s3 = __ldcs(d_slot + i0 + 4*v + 3);
        float r0 = (float)__ldcg(hw + 2*s0 + 1);
        float r1 = (float)__ldcg(hw + 2*s1 + 1);
        float r2 = (float)__ldcg(hw + 2*s2 + 1);
        float r3 = (float)__ldcg(hw + 2*s3 + 1);
        float4 r4 = make_float4(r0, r1, r2, r3);
        __stcs((float4*)(out + OFF_UL + i0 + 4*v), r4);
    }
}

// ---------------------------------------------------------------------------
// K5: fixup — ULI SENT tail + (dormant) deficient-batch non-first fill
__global__ void k_fixup(const float* __restrict__ x, float* __restrict__ out) {
    int blk = blockIdx.x;
    int t = threadIdx.x;
    if (blk >= BATCH) {
        int U = (int)(d_bbase[BATCH] & VALMASK);
        int nb = gridDim.x - BATCH;
        for (int i = U + (blk - BATCH) * blockDim.x + t; i < BN; i += nb * blockDim.x)
            __stcs(&out[OFF_ULI + i], (float)BN);
        return;
    }
    int pb0 = (int)(d_bbase[blk] & VALMASK);
    int pb1 = (int)(d_bbase[blk + 1] & VALMASK);
    int Kb = pb1 - pb0;
    if (Kb >= TSEL) return;   // normal case

    // Dormant slow path: sequential chunked scan over this batch's points
    __shared__ int s_run;
    __shared__ int cw[8];
    const unsigned* hlow = (const unsigned*)d_h;
    if (t == 0) s_run = 0;
    __syncthreads();
    for (int base = 0; base < NPTS; base += SCANT) {
        int il = base + t;
        int i = blk * NPTS + il;
        int sl = d_slot[i];
        int isf = (__ldcg(hlow + 2*sl) == (unsigned)i);
        int lane = t & 31, wid = t >> 5;
        int incv = isf;
        #pragma unroll
        for (int o = 1; o < 32; o <<= 1) {
            int u = __shfl_up_sync(0xFFFFFFFFu, incv, o);
            if (lane >= o) incv += u;
        }
        if (lane == 31) cw[wid] = incv;
        __syncthreads();
        int woff = 0;
        for (int k = 0; k < wid; k++) woff += cw[k];
        int r = s_run + woff + incv - isf;
        if (!isf) {
            int tt = Kb + (il - r);
            if (tt < TSEL) {
                float y0 = CELL * rintf(__fdiv_rn(__ldg(&x[3*i+0]), CELL));
                float y1 = CELL * rintf(__fdiv_rn(__ldg(&x[3*i+1]), CELL));
                float y2 = CELL * rintf(__fdiv_rn(__ldg(&x[3*i+2]), CELL));
                int o = blk * TSEL + tt;
                out[OFF_Y + 3*o + 0] = y0;
                out[OFF_Y + 3*o + 1] = y1;
                out[OFF_Y + 3*o + 2] = y2;
                out[OFF_IDX + 2*o + 0] = (float)blk;
                out[OFF_IDX + 2*o + 1] = (float)il;
                out[OFF_MASK + o] = 0.0f;
            }
        }
        __syncthreads();
        if (t == 0) {
            int tot = 0;
            #pragma unroll
            for (int k = 0; k < 8; k++) tot += cw[k];
            s_run += tot;
        }
        __syncthreads();
    }
}

// ---------------------------------------------------------------------------
extern "C" void kernel_launch(void* const* d_in, const int* in_sizes, int n_in,
                              void* d_out, int out_size) {
    const float* x = (const float*)d_in[0];
    float* out = (float*)d_out;
    (void)in_sizes; (void)n_in; (void)out_size;

    k_init  <<<2048, 512>>>();
    k_insert<<<BN / 256, 256>>>(x);
    k_fused <<<NBLK, SCANT>>>(out);
    k_ul    <<<NBLK, SCANT>>>(out);
    k_fixup <<<BATCH + 64, SCANT>>>(x, out);
}

// round 9
// speedup vs baseline: 4.1567x; 1.0618x over previous
#include <cuda_runtime.h>
#include <limits.h>
#include <stdint.h>

typedef unsigned long long u64;

// Problem constants
#define BATCH 32
#define NPTS  131072            // 2^17
#define BN    (BATCH*NPTS)      // 4194304
#define TSEL  32768
#define CELL  0.05f

// Hash: 2^23 slots of one u64 (key<<32 | minIdx)
#define HBITS 23
#define HSIZE (1<<HBITS)
#define HMASK (HSIZE-1)
#define EMPTY64 0xFFFFFFFFFFFFFFFFull

// Scan config: 1024 blocks x 4096 elements (256 thr x 16)
#define NBLK  1024
#define CHUNK 4096
#define SCANT 256
#define ITEMS 16

// Lookback state flags
#define FLAG1 (1ull << 62)
#define FLAG2 (2ull << 62)
#define SFMASK (3ull << 62)
#define PUBBIT (1ull << 63)
#define VALMASK 0x3FFFFFFFull
#define NOTFI 0xFFFFFFFFu

// Output layout (flattened, concatenated, all f32)
#define OFF_Y    0
#define OFF_IDX  (BATCH*TSEL*3)
#define OFF_MASK (OFF_IDX + BATCH*TSEL*2)
#define OFF_UL   (OFF_MASK + BATCH*TSEL)
#define OFF_ULI  (OFF_UL + BN)

// Scratch
__device__ u64 d_h[HSIZE];             // (key<<32)|minIdx
__device__ unsigned d_slot[BN];        // slot idx; after k_fused: fi (non-first) / NOTFI
__device__ u64 d_state[NBLK];
__device__ u64 d_bbase[BATCH+1];
__device__ unsigned d_ticket;

__device__ __forceinline__ int quant(float v) {
    return (int)rintf(__fdiv_rn(v, CELL));
}
__device__ __forceinline__ unsigned mkkey(int b, int q0, int q1, int q2) {
    return ((unsigned)b << 27) | ((unsigned)(q0 + 256) << 18)
         | ((unsigned)(q1 + 256) << 9) | (unsigned)(q2 + 256);
}
__device__ __forceinline__ unsigned khash(unsigned k) {
    return (k * 2654435761u) >> (32 - HBITS);
}

// ---------------------------------------------------------------------------
// K1: init hash table + lookback state
__global__ void k_init() {
    unsigned i = blockIdx.x * blockDim.x + threadIdx.x;
    unsigned stride = gridDim.x * blockDim.x;
    ulonglong2* p = (ulonglong2*)d_h;
    const unsigned n = HSIZE / 2;
    for (unsigned j = i; j < n; j += stride)
        p[j] = make_ulonglong2(EMPTY64, EMPTY64);
    if (i < NBLK) d_state[i] = 0;
    if (i <= BATCH) d_bbase[i] = 0;
    if (i == 0) d_ticket = 0;
}

// ---------------------------------------------------------------------------
// K2: insert, CAS-first probing
__global__ void k_insert(const float* __restrict__ x) {
    int i = blockIdx.x * blockDim.x + threadIdx.x;   // [0, BN)
    float x0 = __ldcs(&x[3*i+0]);
    float x1 = __ldcs(&x[3*i+1]);
    float x2 = __ldcs(&x[3*i+2]);
    int q0 = quant(x0), q1 = quant(x1), q2 = quant(x2);
    int b = i >> 17;
    unsigned key = mkkey(b, q0, q1, q2);
    u64 val = ((u64)key << 32) | (unsigned)i;
    unsigned h = khash(key);
    while (true) {
        u64 old = atomicCAS(&d_h[h], EMPTY64, val);
        if (old == EMPTY64) break;
        if ((unsigned)(old >> 32) == key) {
            if ((unsigned)old > (unsigned)i)
                atomicMin(&d_h[h], val);
            break;
        }
        h = (h + 1) & HMASK;
    }
    __stcs(&d_slot[i], h);
}

// ---------------------------------------------------------------------------
// K3: fused flags + decoupled-lookback scan + scatters
//     outputs: ULI, UL (firsts, coalesced), y/idx/mask (selected),
//              d_slot[i] <- fi (non-first) / NOTFI (first)
__global__ void __launch_bounds__(SCANT) k_fused(float* __restrict__ out) {
    __shared__ int s_tb;
    __shared__ int wsum[8];
    __shared__ int wexc[8];
    __shared__ int s_total;
    __shared__ unsigned s_excl, s_pb;

    int t = threadIdx.x;
    if (t == 0) s_tb = (int)atomicAdd(&d_ticket, 1u);
    __syncthreads();
    int tb = s_tb;
    int i0 = tb * CHUNK + t * ITEMS;

    unsigned ss[ITEMS];
    #pragma unroll
    for (int v = 0; v < 4; v++) {
        uint4 sv = *(const uint4*)(d_slot + i0 + 4*v);
        ss[4*v+0] = sv.x; ss[4*v+1] = sv.y; ss[4*v+2] = sv.z; ss[4*v+3] = sv.w;
    }

    // full entry read: low -> fi (flag: fi==i), high -> key (y decode)
    unsigned hk[ITEMS];
    unsigned fi[ITEMS];
    unsigned fmask = 0;
    int pre[ITEMS];
    int c = 0;
    #pragma unroll
    for (int e = 0; e < ITEMS; e++) {
        u64 cur = __ldcg(&d_h[ss[e]]);
        fi[e] = (unsigned)cur;
        hk[e] = (unsigned)(cur >> 32);
        unsigned f = (fi[e] == (unsigned)(i0 + e));
        fmask |= f << e;
        pre[e] = c;
        c += (int)f;
    }

    // block scan of per-thread counts
    int lane = t & 31, wid = t >> 5;
    int inc = c;
    #pragma unroll
    for (int o = 1; o < 32; o <<= 1) {
        int u = __shfl_up_sync(0xFFFFFFFFu, inc, o);
        if (lane >= o) inc += u;
    }
    if (lane == 31) wsum[wid] = inc;
    __syncthreads();
    if (t < 8) {
        int val = wsum[t];
        int ic = val;
        #pragma unroll
        for (int o = 1; o < 8; o <<= 1) {
            int u = __shfl_up_sync(0xFFu, ic, o);
            if (t >= o) ic += u;
        }
        wexc[t] = ic - val;
        if (t == 7) s_total = ic;
    }
    __syncthreads();
    int agg = s_total;

    // decoupled lookback (thread 0)
    if (t == 0) {
        unsigned excl = 0;
        if (tb == 0) {
            __threadfence();
            atomicExch(&d_state[0], FLAG2 | (u64)agg);
        } else {
            atomicExch(&d_state[tb], FLAG1 | (u64)agg);
            int j = tb - 1;
            while (true) {
                u64 s = *(volatile u64*)&d_state[j];
                u64 f = s & SFMASK;
                if (f == 0) continue;
                excl += (unsigned)(s & VALMASK);
                if (f == FLAG2) break;
                j--;
            }
            __threadfence();
            atomicExch(&d_state[tb], FLAG2 | (u64)(excl + (unsigned)agg));
        }
        int m = tb >> 5;
        unsigned pbv;
        if ((tb & 31) == 0) {
            __threadfence();
            atomicExch(&d_bbase[m], PUBBIT | (u64)excl);
            pbv = excl;
        } else {
            while (true) {
                u64 s = *(volatile u64*)&d_bbase[m];
                if (s & PUBBIT) { pbv = (unsigned)(s & VALMASK); break; }
            }
        }
        if (tb == NBLK - 1) {
            __threadfence();
            atomicExch(&d_bbase[BATCH], PUBBIT | (u64)(excl + (unsigned)agg));
        }
        s_excl = excl;
        s_pb = pbv;
    }
    __syncthreads();

    int thOff = (int)s_excl + wexc[wid] + (inc - c);
    int pb = (int)s_pb;
    int b = tb >> 5;

    // overwrite d_slot with fi (non-first) / NOTFI (first) — coalesced uint4
    #pragma unroll
    for (int v = 0; v < 4; v++) {
        uint4 o4;
        o4.x = ((fmask >> (4*v+0)) & 1) ? NOTFI : fi[4*v+0];
        o4.y = ((fmask >> (4*v+1)) & 1) ? NOTFI : fi[4*v+1];
        o4.z = ((fmask >> (4*v+2)) & 1) ? NOTFI : fi[4*v+2];
        o4.w = ((fmask >> (4*v+3)) & 1) ? NOTFI : fi[4*v+3];
        __stcs((uint4*)(d_slot + i0 + 4*v), o4);
    }

    // scatter: firsts — UL (own index, mostly-dense), ULI, selected y/idx/mask
    #pragma unroll
    for (int e = 0; e < ITEMS; e++) {
        if ((fmask >> e) & 1) {
            int i  = i0 + e;
            int p  = thOff + pre[e];
            out[OFF_UL + i] = (float)p;
            __stcs(&out[OFF_ULI + p], (float)i);
            int r = p - pb;
            if (r < TSEL) {
                unsigned key = hk[e];
                int il = i & (NPTS - 1);
                float y0 = CELL * (float)((int)((key >> 18) & 511) - 256);
                float y1 = CELL * (float)((int)((key >> 9) & 511) - 256);
                float y2 = CELL * (float)((int)(key & 511) - 256);
                int o = b * TSEL + r;
                __stcs(&out[OFF_Y + 3*o + 0], y0);
                __stcs(&out[OFF_Y + 3*o + 1], y1);
                __stcs(&out[OFF_Y + 3*o + 2], y2);
                __stcs(&out[OFF_IDX + 2*o + 0], (float)b);
                __stcs(&out[OFF_IDX + 2*o + 1], (float)il);
                __stcs(&out[OFF_MASK + o], 1.0f);
            }
        }
    }
}

// ---------------------------------------------------------------------------
// K4: ul_idx for non-firsts: gather rank from L2-resident UL region via fi
__global__ void k_ul(float* __restrict__ out) {
    int t = threadIdx.x;
    int i0 = blockIdx.x * CHUNK + t * ITEMS;
    #pragma unroll
    for (int v = 0; v < 4; v++) {
        uint4 f4 = *(const uint4*)(d_slot + i0 + 4*v);
        unsigned f[4] = {f4.x, f4.y, f4.z, f4.w};
        #pragma unroll
        for (int e = 0; e < 4; e++) {
            if (f[e] != NOTFI) {
                float rank = __ldcg(&out[OFF_UL + f[e]]);
                out[OFF_UL + i0 + 4*v + e] = rank;
            }
        }
    }
}

// ---------------------------------------------------------------------------
// K5: fixup — ULI SENT tail + (dormant) deficient-batch non-first fill
__global__ void k_fixup(const float* __restrict__ x, float* __restrict__ out) {
    int blk = blockIdx.x;
    int t = threadIdx.x;
    if (blk >= BATCH) {
        int U = (int)(d_bbase[BATCH] & VALMASK);
        int nb = gridDim.x - BATCH;
        for (int i = U + (blk - BATCH) * blockDim.x + t; i < BN; i += nb * blockDim.x)
            __stcs(&out[OFF_ULI + i], (float)BN);
        return;
    }
    int pb0 = (int)(d_bbase[blk] & VALMASK);
    int pb1 = (int)(d_bbase[blk + 1] & VALMASK);
    int Kb = pb1 - pb0;
    if (Kb >= TSEL) return;   // normal case

    // Dormant slow path: sequential chunked scan over this batch's points
    // (d_slot now holds fi/NOTFI: first <=> NOTFI)
    __shared__ int s_run;
    __shared__ int cw[8];
    if (t == 0) s_run = 0;
    __syncthreads();
    for (int base = 0; base < NPTS; base += SCANT) {
        int il = base + t;
        int i = blk * NPTS + il;
        int isf = (d_slot[i] == NOTFI);
        int lane = t & 31, wid = t >> 5;
        int incv = isf;
        #pragma unroll
        for (int o = 1; o < 32; o <<= 1) {
            int u = __shfl_up_sync(0xFFFFFFFFu, incv, o);
            if (lane >= o) incv += u;
        }
        if (lane == 31) cw[wid] = incv;
        __syncthreads();
        int woff = 0;
        for (int k = 0; k < wid; k++) woff += cw[k];
        int r = s_run + woff + incv - isf;
        if (!isf) {
            int tt = Kb + (il - r);
            if (tt < TSEL) {
                float y0 = CELL * rintf(__fdiv_rn(__ldg(&x[3*i+0]), CELL));
                float y1 = CELL * rintf(__fdiv_rn(__ldg(&x[3*i+1]), CELL));
                float y2 = CELL * rintf(__fdiv_rn(__ldg(&x[3*i+2]), CELL));
                int o = blk * TSEL + tt;
                out[OFF_Y + 3*o + 0] = y0;
                out[OFF_Y + 3*o + 1] = y1;
                out[OFF_Y + 3*o + 2] = y2;
                out[OFF_IDX + 2*o + 0] = (float)blk;
                out[OFF_IDX + 2*o + 1] = (float)il;
                out[OFF_MASK + o] = 0.0f;
            }
        }
        __syncthreads();
        if (t == 0) {
            int tot = 0;
            #pragma unroll
            for (int k = 0; k < 8; k++) tot += cw[k];
            s_run += tot;
        }
        __syncthreads();
    }
}

// ---------------------------------------------------------------------------
extern "C" void kernel_launch(void* const* d_in, const int* in_sizes, int n_in,
                              void* d_out, int out_size) {
    const float* x = (const float*)d_in[0];
    float* out = (float*)d_out;
    (void)in_sizes; (void)n_in; (void)out_size;

    k_init  <<<2048, 512>>>();
    k_insert<<<BN / 256, 256>>>(x);
    k_fused <<<NBLK, SCANT>>>(out);
    k_ul    <<<NBLK, SCANT>>>(out);
    k_fixup <<<BATCH + 64, SCANT>>>(x, out);
}